// round 2
// baseline (speedup 1.0000x reference)
#include <cuda_runtime.h>
#include <math.h>

// Problem: output [B=2, C=8, H=128, W=128, D=128] fp32.
// t = where(x > 0.5, x, 0); per-(b,c): s = sum t, sy = sum t*(h/H), sx = sum t*(w/W), sz = sum t*(d/D)
// centroids = s?/s; loss = sum over 8 relations of mean_b((d - gt)^2) for each of y,x,z (nan/inf -> 0).

#define NCH        16          // B*C
#define CH_ELEMS   (128*128*128)
#define BLK_PER_CH 128
#define THREADS    256
#define ELEMS_PER_BLOCK (CH_ELEMS / BLK_PER_CH)   // 16384
#define VEC_PER_BLOCK   (ELEMS_PER_BLOCK / 4)      // 4096

// partials[ch][blk][4] : s, sy, sx, sz
__device__ float g_partials[NCH * BLK_PER_CH * 4];

__global__ void __launch_bounds__(THREADS)
gsl_reduce_kernel(const float* __restrict__ in) {
    const int ch  = blockIdx.y;
    const int blk = blockIdx.x;
    const float* base = in + (size_t)ch * CH_ELEMS;
    const int start = blk * ELEMS_PER_BLOCK;
    const float inv = 1.0f / 128.0f;

    float s = 0.f, sy = 0.f, sx = 0.f, sz = 0.f;

    const float4* vbase = reinterpret_cast<const float4*>(base) + (start >> 2);
    for (int i = threadIdx.x; i < VEC_PER_BLOCK; i += THREADS) {
        float4 v = vbase[i];
        int idx = start + (i << 2);
        int z = idx & 127;
        int w = (idx >> 7) & 127;
        int h = idx >> 14;
        float cy  = (float)h * inv;
        float cx  = (float)w * inv;
        float cz0 = (float)z * inv;

        float t0 = v.x > 0.5f ? v.x : 0.f;
        float t1 = v.y > 0.5f ? v.y : 0.f;
        float t2 = v.z > 0.5f ? v.z : 0.f;
        float t3 = v.w > 0.5f ? v.w : 0.f;

        float ts = (t0 + t1) + (t2 + t3);
        s  += ts;
        sy += ts * cy;
        sx += ts * cx;
        sz += t0 * cz0 + t1 * (cz0 + inv) + t2 * (cz0 + 2.f * inv) + t3 * (cz0 + 3.f * inv);
    }

    // warp reduce
    #pragma unroll
    for (int off = 16; off > 0; off >>= 1) {
        s  += __shfl_down_sync(0xFFFFFFFFu, s,  off);
        sy += __shfl_down_sync(0xFFFFFFFFu, sy, off);
        sx += __shfl_down_sync(0xFFFFFFFFu, sx, off);
        sz += __shfl_down_sync(0xFFFFFFFFu, sz, off);
    }

    __shared__ float sh[THREADS / 32][4];
    int lane = threadIdx.x & 31;
    int wid  = threadIdx.x >> 5;
    if (lane == 0) {
        sh[wid][0] = s; sh[wid][1] = sy; sh[wid][2] = sx; sh[wid][3] = sz;
    }
    __syncthreads();

    if (wid == 0) {
        float a = (lane < THREADS / 32) ? sh[lane][0] : 0.f;
        float b = (lane < THREADS / 32) ? sh[lane][1] : 0.f;
        float c = (lane < THREADS / 32) ? sh[lane][2] : 0.f;
        float d = (lane < THREADS / 32) ? sh[lane][3] : 0.f;
        #pragma unroll
        for (int off = 4; off > 0; off >>= 1) {
            a += __shfl_down_sync(0xFFFFFFFFu, a, off);
            b += __shfl_down_sync(0xFFFFFFFFu, b, off);
            c += __shfl_down_sync(0xFFFFFFFFu, c, off);
            d += __shfl_down_sync(0xFFFFFFFFu, d, off);
        }
        if (lane == 0) {
            float* p = &g_partials[(ch * BLK_PER_CH + blk) * 4];
            p[0] = a; p[1] = b; p[2] = c; p[3] = d;
        }
    }
}

__constant__ int   c_rel_i[8]  = {0, 1, 2, 3, 4, 5, 6, 0};
__constant__ int   c_rel_j[8]  = {1, 2, 3, 4, 5, 6, 7, 7};
__constant__ float c_gt_y[8]   = { 0.1f,  0.0f, -0.1f,  0.0f,  0.05f,  0.0f, 0.1f, -0.05f};
__constant__ float c_gt_x[8]   = { 0.0f,  0.1f,  0.05f, 0.0f, -0.05f,  0.1f, 0.0f,  0.05f};
__constant__ float c_gt_z[8]   = { 0.05f, 0.0f,  0.0f,  0.1f,  0.0f, -0.1f, 0.0f,  0.05f};

__device__ __forceinline__ float nan0(float x) { return isfinite(x) ? x : 0.f; }

__global__ void __launch_bounds__(128)
gsl_final_kernel(float* __restrict__ out, int out_size) {
    __shared__ float cen_y[NCH], cen_x[NCH], cen_z[NCH];

    int lane = threadIdx.x & 31;
    int wid  = threadIdx.x >> 5;   // 4 warps

    // each warp handles 4 channels; within a channel, 128 partials reduced by
    // 32 lanes x 4 sequential loads (deterministic order)
    for (int ch = wid; ch < NCH; ch += 4) {
        float s = 0.f, sy = 0.f, sx = 0.f, sz = 0.f;
        #pragma unroll
        for (int k = 0; k < 4; k++) {
            const float* p = &g_partials[(ch * BLK_PER_CH + k * 32 + lane) * 4];
            s  += p[0]; sy += p[1]; sx += p[2]; sz += p[3];
        }
        #pragma unroll
        for (int off = 16; off > 0; off >>= 1) {
            s  += __shfl_down_sync(0xFFFFFFFFu, s,  off);
            sy += __shfl_down_sync(0xFFFFFFFFu, sy, off);
            sx += __shfl_down_sync(0xFFFFFFFFu, sx, off);
            sz += __shfl_down_sync(0xFFFFFFFFu, sz, off);
        }
        if (lane == 0) {
            cen_y[ch] = sy / s;
            cen_x[ch] = sx / s;
            cen_z[ch] = sz / s;
        }
    }
    __syncthreads();

    if (threadIdx.x == 0) {
        float loss = 0.f;
        #pragma unroll
        for (int r = 0; r < 8; r++) {
            int ci = c_rel_i[r], cj = c_rel_j[r];
            float my = 0.f, mx = 0.f, mz = 0.f;
            #pragma unroll
            for (int b = 0; b < 2; b++) {
                int ii = b * 8 + ci, jj = b * 8 + cj;
                float dy = nan0(cen_y[ii] - cen_y[jj] - c_gt_y[r]);
                float dx = nan0(cen_x[ii] - cen_x[jj] - c_gt_x[r]);
                float dz = nan0(cen_z[ii] - cen_z[jj] - c_gt_z[r]);
                my += dy * dy; mx += dx * dx; mz += dz * dz;
            }
            loss += 0.5f * (my + mx + mz);   // mean over B=2
        }
        out[0] = loss;
    }
    // zero any extra output slots (d_out is poisoned)
    for (int i = 1 + (int)threadIdx.x; i < out_size; i += 128) out[i] = 0.f;
}

extern "C" void kernel_launch(void* const* d_in, const int* in_sizes, int n_in,
                              void* d_out, int out_size) {
    const float* in = (const float*)d_in[0];
    dim3 grid(BLK_PER_CH, NCH);
    gsl_reduce_kernel<<<grid, THREADS>>>(in);
    gsl_final_kernel<<<1, 128>>>((float*)d_out, out_size);
}

// round 3
// speedup vs baseline: 1.0850x; 1.0850x over previous
#include <cuda_runtime.h>
#include <math.h>

// Problem: output [B=2, C=8, H=128, W=128, D=128] fp32.
// t = where(x > 0.5, x, 0); per-(b,c): s = sum t, sy = sum t*(h/H), sx = sum t*(w/W), sz = sum t*(d/D)
// centroids = s?/s; loss = sum over 8 relations of mean_b((d - gt)^2) per axis (nan/inf -> 0).
//
// Single fused kernel: 2048 blocks reduce, last block finalizes.

#define NCH        16          // B*C
#define CH_ELEMS   (128*128*128)
#define BLK_PER_CH 128
#define NBLOCKS    (NCH * BLK_PER_CH)              // 2048
#define THREADS    256
#define ELEMS_PER_BLOCK (CH_ELEMS / BLK_PER_CH)    // 16384
#define VEC_PER_BLOCK   (ELEMS_PER_BLOCK / 4)      // 4096

// partials[ch][blk][4] : s, sy, sx, sz
__device__ float g_partials[NCH * BLK_PER_CH * 4];
__device__ int   g_count = 0;

__constant__ int   c_rel_i[8]  = {0, 1, 2, 3, 4, 5, 6, 0};
__constant__ int   c_rel_j[8]  = {1, 2, 3, 4, 5, 6, 7, 7};
__constant__ float c_gt_y[8]   = { 0.1f,  0.0f, -0.1f,  0.0f,  0.05f,  0.0f, 0.1f, -0.05f};
__constant__ float c_gt_x[8]   = { 0.0f,  0.1f,  0.05f, 0.0f, -0.05f,  0.1f, 0.0f,  0.05f};
__constant__ float c_gt_z[8]   = { 0.05f, 0.0f,  0.0f,  0.1f,  0.0f, -0.1f, 0.0f,  0.05f};

__device__ __forceinline__ float nan0(float x) { return isfinite(x) ? x : 0.f; }

__global__ void __launch_bounds__(THREADS)
gsl_fused_kernel(const float* __restrict__ in, float* __restrict__ out, int out_size) {
    const int ch  = blockIdx.x >> 7;          // blockIdx.x / BLK_PER_CH
    const int blk = blockIdx.x & 127;
    const int start = blk * ELEMS_PER_BLOCK;
    const float inv = 1.0f / 128.0f;

    float s = 0.f, sy = 0.f, sx = 0.f, sz = 0.f;

    const float4* vbase = reinterpret_cast<const float4*>(in + (size_t)ch * CH_ELEMS)
                          + (start >> 2);

    // 4 iterations x 4 front-batched independent LDG.128 per thread
    #pragma unroll
    for (int it = 0; it < VEC_PER_BLOCK / (THREADS * 4); ++it) {
        const int j0 = it * (THREADS * 4) + threadIdx.x;
        float4 v0 = vbase[j0];
        float4 v1 = vbase[j0 + THREADS];
        float4 v2 = vbase[j0 + 2 * THREADS];
        float4 v3 = vbase[j0 + 3 * THREADS];

        #pragma unroll
        for (int u = 0; u < 4; ++u) {
            float4 v = (u == 0) ? v0 : (u == 1) ? v1 : (u == 2) ? v2 : v3;
            int idx = start + ((j0 + u * THREADS) << 2);
            int z = idx & 127;
            int w = (idx >> 7) & 127;
            int h = idx >> 14;
            float cy  = (float)h * inv;
            float cx  = (float)w * inv;
            float cz0 = (float)z * inv;

            float t0 = v.x > 0.5f ? v.x : 0.f;
            float t1 = v.y > 0.5f ? v.y : 0.f;
            float t2 = v.z > 0.5f ? v.z : 0.f;
            float t3 = v.w > 0.5f ? v.w : 0.f;

            float ts = (t0 + t1) + (t2 + t3);
            s  += ts;
            sy += ts * cy;
            sx += ts * cx;
            sz += t0 * cz0 + t1 * (cz0 + inv) + t2 * (cz0 + 2.f * inv) + t3 * (cz0 + 3.f * inv);
        }
    }

    // block reduce
    #pragma unroll
    for (int off = 16; off > 0; off >>= 1) {
        s  += __shfl_down_sync(0xFFFFFFFFu, s,  off);
        sy += __shfl_down_sync(0xFFFFFFFFu, sy, off);
        sx += __shfl_down_sync(0xFFFFFFFFu, sx, off);
        sz += __shfl_down_sync(0xFFFFFFFFu, sz, off);
    }

    __shared__ float sh[THREADS / 32][4];
    const int lane = threadIdx.x & 31;
    const int wid  = threadIdx.x >> 5;
    if (lane == 0) {
        sh[wid][0] = s; sh[wid][1] = sy; sh[wid][2] = sx; sh[wid][3] = sz;
    }
    __syncthreads();

    __shared__ bool is_last;
    if (wid == 0) {
        float a = (lane < THREADS / 32) ? sh[lane][0] : 0.f;
        float b = (lane < THREADS / 32) ? sh[lane][1] : 0.f;
        float c = (lane < THREADS / 32) ? sh[lane][2] : 0.f;
        float d = (lane < THREADS / 32) ? sh[lane][3] : 0.f;
        #pragma unroll
        for (int off = 4; off > 0; off >>= 1) {
            a += __shfl_down_sync(0xFFFFFFFFu, a, off);
            b += __shfl_down_sync(0xFFFFFFFFu, b, off);
            c += __shfl_down_sync(0xFFFFFFFFu, c, off);
            d += __shfl_down_sync(0xFFFFFFFFu, d, off);
        }
        if (lane == 0) {
            float* p = &g_partials[(ch * BLK_PER_CH + blk) * 4];
            p[0] = a; p[1] = b; p[2] = c; p[3] = d;
            __threadfence();                    // make partials visible device-wide
            int prev = atomicAdd(&g_count, 1);
            is_last = (prev == NBLOCKS - 1);
        }
    }
    __syncthreads();

    if (!is_last) return;

    // ---- final reduction: this block only ----
    __shared__ float cen_y[NCH], cen_x[NCH], cen_z[NCH];

    // 8 warps: warp w handles channels w and w+8; 128 partials per channel,
    // 4 per lane, volatile loads (bypass possibly stale L1).
    for (int c = wid; c < NCH; c += THREADS / 32) {
        float a = 0.f, b = 0.f, cc = 0.f, d = 0.f;
        #pragma unroll
        for (int k = 0; k < 4; k++) {
            volatile const float* p = &g_partials[(c * BLK_PER_CH + k * 32 + lane) * 4];
            a += p[0]; b += p[1]; cc += p[2]; d += p[3];
        }
        #pragma unroll
        for (int off = 16; off > 0; off >>= 1) {
            a  += __shfl_down_sync(0xFFFFFFFFu, a,  off);
            b  += __shfl_down_sync(0xFFFFFFFFu, b,  off);
            cc += __shfl_down_sync(0xFFFFFFFFu, cc, off);
            d  += __shfl_down_sync(0xFFFFFFFFu, d,  off);
        }
        if (lane == 0) {
            cen_y[c] = b / a;
            cen_x[c] = cc / a;
            cen_z[c] = d / a;
        }
    }
    __syncthreads();

    if (threadIdx.x == 0) {
        float loss = 0.f;
        #pragma unroll
        for (int r = 0; r < 8; r++) {
            int ci = c_rel_i[r], cj = c_rel_j[r];
            float my = 0.f, mx = 0.f, mz = 0.f;
            #pragma unroll
            for (int b = 0; b < 2; b++) {
                int ii = b * 8 + ci, jj = b * 8 + cj;
                float dy = nan0(cen_y[ii] - cen_y[jj] - c_gt_y[r]);
                float dx = nan0(cen_x[ii] - cen_x[jj] - c_gt_x[r]);
                float dz = nan0(cen_z[ii] - cen_z[jj] - c_gt_z[r]);
                my += dy * dy; mx += dx * dx; mz += dz * dz;
            }
            loss += 0.5f * (my + mx + mz);   // mean over B=2
        }
        out[0] = loss;
        g_count = 0;                          // reset for next graph replay
    }
    // zero any extra output slots (d_out is poisoned)
    for (int i = 1 + (int)threadIdx.x; i < out_size; i += THREADS) out[i] = 0.f;
}

extern "C" void kernel_launch(void* const* d_in, const int* in_sizes, int n_in,
                              void* d_out, int out_size) {
    const float* in = (const float*)d_in[0];
    gsl_fused_kernel<<<NBLOCKS, THREADS>>>(in, (float*)d_out, out_size);
}

// round 4
// speedup vs baseline: 1.1380x; 1.0489x over previous
#include <cuda_runtime.h>
#include <math.h>

// output [B=2, C=8, H=128, W=128, D=128] fp32.
// t = where(x > 0.5, x, 0); per-(b,c): s = sum t, sy = sum t*(h/H), sx, sz analog.
// centroids = s?/s; loss = sum over 8 relations of mean_b((diff - gt)^2), nan/inf->0.
//
// One block per (ch, h) slice (16384 elems): cy constant per block, z constant
// per thread, cx linear in the unroll index -> no coordinate math in the loop.

#define NCH        16
#define H_SLICES   128
#define NBLOCKS    (NCH * H_SLICES)            // 2048
#define THREADS    256
#define SLICE_VEC  4096                         // float4 per slice

__device__ float g_partials[NBLOCKS * 4];       // [ch][h][{s,sy,sx,sz}]
__device__ int   g_count = 0;

__constant__ int   c_rel_i[8] = {0, 1, 2, 3, 4, 5, 6, 0};
__constant__ int   c_rel_j[8] = {1, 2, 3, 4, 5, 6, 7, 7};
__constant__ float c_gt_y[8]  = { 0.1f,  0.0f, -0.1f,  0.0f,  0.05f,  0.0f, 0.1f, -0.05f};
__constant__ float c_gt_x[8]  = { 0.0f,  0.1f,  0.05f, 0.0f, -0.05f,  0.1f, 0.0f,  0.05f};
__constant__ float c_gt_z[8]  = { 0.05f, 0.0f,  0.0f,  0.1f,  0.0f, -0.1f, 0.0f,  0.05f};

__device__ __forceinline__ float nan0(float x) { return isfinite(x) ? x : 0.f; }

__global__ void __launch_bounds__(THREADS)
gsl_fused_kernel(const float* __restrict__ in, float* __restrict__ out, int out_size) {
    const int tid = threadIdx.x;
    const float inv = 1.0f / 128.0f;

    const float4* vb = reinterpret_cast<const float4*>(in) + ((size_t)blockIdx.x * SLICE_VEC);

    // thread-constant z weights: z = (tid & 31) * 4
    const float cz0 = (float)((tid & 31) << 2) * inv;
    const float w0 = cz0, w1 = cz0 + inv, w2 = cz0 + 2.f * inv, w3 = cz0 + 3.f * inv;
    // cx base: w index = (tid >> 5) + it*32 + u*8
    const float cx0 = (float)(tid >> 5) * inv;

    float s = 0.f, sx = 0.f, sz = 0.f;

    // prefetch-pipelined: 4 loads consumed while next 4 are in flight
    float4 b0 = __ldcs(&vb[tid]);
    float4 b1 = __ldcs(&vb[tid + 256]);
    float4 b2 = __ldcs(&vb[tid + 512]);
    float4 b3 = __ldcs(&vb[tid + 768]);

    #pragma unroll
    for (int it = 0; it < 4; ++it) {
        float4 n0, n1, n2, n3;
        if (it < 3) {
            const int o = (it + 1) * 1024 + tid;
            n0 = __ldcs(&vb[o]);
            n1 = __ldcs(&vb[o + 256]);
            n2 = __ldcs(&vb[o + 512]);
            n3 = __ldcs(&vb[o + 768]);
        }

        #pragma unroll
        for (int u = 0; u < 4; ++u) {
            float4 v = (u == 0) ? b0 : (u == 1) ? b1 : (u == 2) ? b2 : b3;
            const float cx = cx0 + (float)(it * 32 + u * 8) * inv;

            float t0 = v.x > 0.5f ? v.x : 0.f;
            float t1 = v.y > 0.5f ? v.y : 0.f;
            float t2 = v.z > 0.5f ? v.z : 0.f;
            float t3 = v.w > 0.5f ? v.w : 0.f;

            float ts = (t0 + t1) + (t2 + t3);
            s += ts;
            sx = fmaf(ts, cx, sx);
            sz = fmaf(t0, w0, fmaf(t1, w1, fmaf(t2, w2, fmaf(t3, w3, sz))));
        }
        b0 = n0; b1 = n1; b2 = n2; b3 = n3;
    }

    // block reduce (s, sx, sz)
    #pragma unroll
    for (int off = 16; off > 0; off >>= 1) {
        s  += __shfl_down_sync(0xFFFFFFFFu, s,  off);
        sx += __shfl_down_sync(0xFFFFFFFFu, sx, off);
        sz += __shfl_down_sync(0xFFFFFFFFu, sz, off);
    }

    __shared__ float sh[THREADS / 32][3];
    const int lane = tid & 31;
    const int wid  = tid >> 5;
    if (lane == 0) { sh[wid][0] = s; sh[wid][1] = sx; sh[wid][2] = sz; }
    __syncthreads();

    __shared__ bool is_last;
    if (wid == 0) {
        float a = (lane < THREADS / 32) ? sh[lane][0] : 0.f;
        float b = (lane < THREADS / 32) ? sh[lane][1] : 0.f;
        float c = (lane < THREADS / 32) ? sh[lane][2] : 0.f;
        #pragma unroll
        for (int off = 4; off > 0; off >>= 1) {
            a += __shfl_down_sync(0xFFFFFFFFu, a, off);
            b += __shfl_down_sync(0xFFFFFFFFu, b, off);
            c += __shfl_down_sync(0xFFFFFFFFu, c, off);
        }
        if (lane == 0) {
            const float cy = (float)(blockIdx.x & 127) * inv;   // h for this slice
            float4 p; p.x = a; p.y = a * cy; p.z = b; p.w = c;
            reinterpret_cast<float4*>(g_partials)[blockIdx.x] = p;
            __threadfence();
            int prev = atomicAdd(&g_count, 1);
            is_last = (prev == NBLOCKS - 1);
        }
    }
    __syncthreads();

    if (!is_last) return;

    // ---- final reduction: this block only ----
    __shared__ float cen_y[NCH], cen_x[NCH], cen_z[NCH];

    for (int c = wid; c < NCH; c += THREADS / 32) {
        float a = 0.f, b = 0.f, cc = 0.f, d = 0.f;
        #pragma unroll
        for (int k = 0; k < 4; k++) {
            volatile const float* p = &g_partials[(c * H_SLICES + k * 32 + lane) * 4];
            a += p[0]; b += p[1]; cc += p[2]; d += p[3];
        }
        #pragma unroll
        for (int off = 16; off > 0; off >>= 1) {
            a  += __shfl_down_sync(0xFFFFFFFFu, a,  off);
            b  += __shfl_down_sync(0xFFFFFFFFu, b,  off);
            cc += __shfl_down_sync(0xFFFFFFFFu, cc, off);
            d  += __shfl_down_sync(0xFFFFFFFFu, d,  off);
        }
        if (lane == 0) {
            cen_y[c] = b / a;
            cen_x[c] = cc / a;
            cen_z[c] = d / a;
        }
    }
    __syncthreads();

    if (tid == 0) {
        float loss = 0.f;
        #pragma unroll
        for (int r = 0; r < 8; r++) {
            int ci = c_rel_i[r], cj = c_rel_j[r];
            float my = 0.f, mx = 0.f, mz = 0.f;
            #pragma unroll
            for (int b = 0; b < 2; b++) {
                int ii = b * 8 + ci, jj = b * 8 + cj;
                float dy = nan0(cen_y[ii] - cen_y[jj] - c_gt_y[r]);
                float dx = nan0(cen_x[ii] - cen_x[jj] - c_gt_x[r]);
                float dz = nan0(cen_z[ii] - cen_z[jj] - c_gt_z[r]);
                my += dy * dy; mx += dx * dx; mz += dz * dz;
            }
            loss += 0.5f * (my + mx + mz);   // mean over B=2
        }
        out[0] = loss;
        g_count = 0;                          // reset for next graph replay
    }
    for (int i = 1 + tid; i < out_size; i += THREADS) out[i] = 0.f;
}

extern "C" void kernel_launch(void* const* d_in, const int* in_sizes, int n_in,
                              void* d_out, int out_size) {
    const float* in = (const float*)d_in[0];
    gsl_fused_kernel<<<NBLOCKS, THREADS>>>(in, (float*)d_out, out_size);
}

// round 5
// speedup vs baseline: 1.2347x; 1.0849x over previous
#include <cuda_runtime.h>
#include <math.h>

// output [B=2, C=8, H=128, W=128, D=128] fp32.
// t = where(x > 0.5, x, 0); per-(b,c): s = sum t, sy = sum t*(h/H), sx, sz analog.
// centroids = s?/s; loss = sum over 8 relations of mean_b((diff - gt)^2), nan/inf->0.
//
// Single-wave persistent layout: 512 blocks, each owns 4 contiguous (ch,h)
// slices (256 KiB). cy constant per slice, z constant per thread, cx linear in
// the unroll index -> no coordinate math in the hot loop. Last block finalizes.

#define NCH        16
#define H_SLICES   128
#define NBLOCKS    512
#define SL_PER_BLK 4
#define THREADS    256
#define SLICE_VEC  4096                         // float4 per slice
#define NBATCH     (SL_PER_BLK * 4)             // 16 batches of 4 loads/thread

__device__ float g_partials[NBLOCKS * 4];       // per block: {s, sy, sx, sz}
__device__ int   g_count = 0;

__constant__ int   c_rel_i[8] = {0, 1, 2, 3, 4, 5, 6, 0};
__constant__ int   c_rel_j[8] = {1, 2, 3, 4, 5, 6, 7, 7};
__constant__ float c_gt_y[8]  = { 0.1f,  0.0f, -0.1f,  0.0f,  0.05f,  0.0f, 0.1f, -0.05f};
__constant__ float c_gt_x[8]  = { 0.0f,  0.1f,  0.05f, 0.0f, -0.05f,  0.1f, 0.0f,  0.05f};
__constant__ float c_gt_z[8]  = { 0.05f, 0.0f,  0.0f,  0.1f,  0.0f, -0.1f, 0.0f,  0.05f};

__device__ __forceinline__ float nan0(float x) { return isfinite(x) ? x : 0.f; }

__global__ void __launch_bounds__(THREADS)
gsl_fused_kernel(const float* __restrict__ in, float* __restrict__ out, int out_size) {
    const int tid = threadIdx.x;
    const float inv = 1.0f / 128.0f;

    const float4* vb = reinterpret_cast<const float4*>(in)
                       + ((size_t)blockIdx.x * (SLICE_VEC * SL_PER_BLK));

    // thread-constant z weights: z = (tid & 31) * 4
    const float cz0 = (float)((tid & 31) << 2) * inv;
    const float w0 = cz0, w1 = cz0 + inv, w2 = cz0 + 2.f * inv, w3 = cz0 + 3.f * inv;
    // cx: w index = (tid >> 5) + it*32 + u*8  (it = batch within slice)
    const float cx0 = (float)(tid >> 5) * inv;

    const int h_base = (blockIdx.x * SL_PER_BLK) & 127;   // h of first slice

    float s = 0.f, sy = 0.f, sx = 0.f, sz = 0.f, s_sl = 0.f;

    float4 b0 = __ldcs(&vb[tid]);
    float4 b1 = __ldcs(&vb[tid + 256]);
    float4 b2 = __ldcs(&vb[tid + 512]);
    float4 b3 = __ldcs(&vb[tid + 768]);

    #pragma unroll
    for (int k = 0; k < NBATCH; ++k) {
        float4 n0, n1, n2, n3;
        if (k < NBATCH - 1) {
            const int o = (k + 1) * 1024 + tid;
            n0 = __ldcs(&vb[o]);
            n1 = __ldcs(&vb[o + 256]);
            n2 = __ldcs(&vb[o + 512]);
            n3 = __ldcs(&vb[o + 768]);
        }

        const int it = k & 3;       // batch within slice (compile-time)
        #pragma unroll
        for (int u = 0; u < 4; ++u) {
            float4 v = (u == 0) ? b0 : (u == 1) ? b1 : (u == 2) ? b2 : b3;
            const float cx = cx0 + (float)(it * 32 + u * 8) * inv;

            float t0 = v.x > 0.5f ? v.x : 0.f;
            float t1 = v.y > 0.5f ? v.y : 0.f;
            float t2 = v.z > 0.5f ? v.z : 0.f;
            float t3 = v.w > 0.5f ? v.w : 0.f;

            float ts = (t0 + t1) + (t2 + t3);
            s_sl += ts;
            sx = fmaf(ts, cx, sx);
            sz = fmaf(t0, w0, fmaf(t1, w1, fmaf(t2, w2, fmaf(t3, w3, sz))));
        }

        if (it == 3) {              // end of slice: fold cy (compile-time branch)
            const float cy = (float)(h_base + (k >> 2)) * inv;
            s += s_sl;
            sy = fmaf(s_sl, cy, sy);
            s_sl = 0.f;
        }
        b0 = n0; b1 = n1; b2 = n2; b3 = n3;
    }

    // block reduce (s, sy, sx, sz)
    #pragma unroll
    for (int off = 16; off > 0; off >>= 1) {
        s  += __shfl_down_sync(0xFFFFFFFFu, s,  off);
        sy += __shfl_down_sync(0xFFFFFFFFu, sy, off);
        sx += __shfl_down_sync(0xFFFFFFFFu, sx, off);
        sz += __shfl_down_sync(0xFFFFFFFFu, sz, off);
    }

    __shared__ float sh[THREADS / 32][4];
    const int lane = tid & 31;
    const int wid  = tid >> 5;
    if (lane == 0) { sh[wid][0] = s; sh[wid][1] = sy; sh[wid][2] = sx; sh[wid][3] = sz; }
    __syncthreads();

    __shared__ bool is_last;
    if (wid == 0) {
        float a = (lane < THREADS / 32) ? sh[lane][0] : 0.f;
        float b = (lane < THREADS / 32) ? sh[lane][1] : 0.f;
        float c = (lane < THREADS / 32) ? sh[lane][2] : 0.f;
        float d = (lane < THREADS / 32) ? sh[lane][3] : 0.f;
        #pragma unroll
        for (int off = 4; off > 0; off >>= 1) {
            a += __shfl_down_sync(0xFFFFFFFFu, a, off);
            b += __shfl_down_sync(0xFFFFFFFFu, b, off);
            c += __shfl_down_sync(0xFFFFFFFFu, c, off);
            d += __shfl_down_sync(0xFFFFFFFFu, d, off);
        }
        if (lane == 0) {
            float4 p; p.x = a; p.y = b; p.z = c; p.w = d;
            reinterpret_cast<float4*>(g_partials)[blockIdx.x] = p;
            __threadfence();
            int prev = atomicAdd(&g_count, 1);
            is_last = (prev == NBLOCKS - 1);
        }
    }
    __syncthreads();

    if (!is_last) return;

    // ---- final reduction: this block only ----
    __shared__ float cen_y[NCH], cen_x[NCH], cen_z[NCH];

    // 32 block-partials per channel: one per lane; 8 warps cover 16 channels.
    for (int c = wid; c < NCH; c += THREADS / 32) {
        volatile const float* p = &g_partials[(c * 32 + lane) * 4];
        float a = p[0], b = p[1], cc = p[2], d = p[3];
        #pragma unroll
        for (int off = 16; off > 0; off >>= 1) {
            a  += __shfl_down_sync(0xFFFFFFFFu, a,  off);
            b  += __shfl_down_sync(0xFFFFFFFFu, b,  off);
            cc += __shfl_down_sync(0xFFFFFFFFu, cc, off);
            d  += __shfl_down_sync(0xFFFFFFFFu, d,  off);
        }
        if (lane == 0) {
            cen_y[c] = b / a;
            cen_x[c] = cc / a;
            cen_z[c] = d / a;
        }
    }
    __syncthreads();

    if (tid == 0) {
        float loss = 0.f;
        #pragma unroll
        for (int r = 0; r < 8; r++) {
            int ci = c_rel_i[r], cj = c_rel_j[r];
            float my = 0.f, mx = 0.f, mz = 0.f;
            #pragma unroll
            for (int b = 0; b < 2; b++) {
                int ii = b * 8 + ci, jj = b * 8 + cj;
                float dy = nan0(cen_y[ii] - cen_y[jj] - c_gt_y[r]);
                float dx = nan0(cen_x[ii] - cen_x[jj] - c_gt_x[r]);
                float dz = nan0(cen_z[ii] - cen_z[jj] - c_gt_z[r]);
                my += dy * dy; mx += dx * dx; mz += dz * dz;
            }
            loss += 0.5f * (my + mx + mz);   // mean over B=2
        }
        out[0] = loss;
        g_count = 0;                          // reset for next graph replay
    }
    for (int i = 1 + tid; i < out_size; i += THREADS) out[i] = 0.f;
}

extern "C" void kernel_launch(void* const* d_in, const int* in_sizes, int n_in,
                              void* d_out, int out_size) {
    const float* in = (const float*)d_in[0];
    gsl_fused_kernel<<<NBLOCKS, THREADS>>>(in, (float*)d_out, out_size);
}